// round 16
// baseline (speedup 1.0000x reference)
#include <cuda_runtime.h>
#include <cuda_bf16.h>
#include <cuda_fp16.h>
#include <cstdint>

#define DIM 128
#define NMAX 100000
#define EMAX 600000
#define SCAN_B 1024

// ---------------- scratch (device globals; no allocations allowed) ----------------
__device__ unsigned long long g_degcnt[NMAX];  // bits[40:64)=in-count, [0:40)=sum(ew*2^20)
__device__ float g_dinv[NMAX];
__device__ __align__(16) __half g_h[(size_t)NMAX * DIM];   // h in fp16 -> L2-resident
__device__ __align__(8) int2 g_offcnt[NMAX];   // (csr offset, count)
__device__ int  g_slot[EMAX];
__device__ unsigned int g_state[128];          // lookback scan state
__device__ __align__(16) int2 g_edges[EMAX];   // (src row, norm as half2 bits)
__device__ __align__(16) __half g_Wt[DIM * DIM];   // W transposed: [n][k], fp16

// ---------------- launch 1: zero degcnt/state + convert W (fp16) ----------------
__global__ void initwsplit_kernel(const float* __restrict__ W, int N) {
    int i = blockIdx.x * blockDim.x + threadIdx.x;
    if (i < N) g_degcnt[i] = 0ULL;
    if (i < 128) g_state[i] = 0u;
    if (i < DIM * DIM) {
        int k = i >> 7, n = i & 127;
        g_Wt[n * DIM + k] = __float2half(W[i]);
    }
}

// ---------------- degree + in-count + slot harvest: ONE packed 64-bit atomic ----------------
__global__ void deg_kernel(const int* __restrict__ col, const float* __restrict__ ew, int E) {
    int e = blockIdx.x * blockDim.x + threadIdx.x;
    if (e < E) {
        int c = col[e];
        unsigned long long inc = (1ULL << 40)
            | (unsigned long long)__float2uint_rn(ew[e] * 1048576.0f);
        unsigned long long old = atomicAdd(&g_degcnt[c], inc);
        g_slot[e] = (int)(old >> 40);
    }
}

// ---------------- single-pass scan (decoupled lookback) + fused dinv ----------------
__global__ __launch_bounds__(SCAN_B) void scanlb_kernel(int N) {
    __shared__ int wsum[32];
    __shared__ int sh_agg;
    __shared__ int sh_prefix;
    int t = threadIdx.x, b = blockIdx.x;
    int i = b * SCAN_B + t;
    int lane = t & 31, wid = t >> 5;

    int v = 0;
    if (i < N) {
        unsigned long long pv = g_degcnt[i];
        v = (int)(pv >> 40);
        float d = (float)(pv & 0xFFFFFFFFFFULL) * (1.0f / 1048576.0f);
        g_dinv[i] = (d > 0.0f) ? rsqrtf(d) : 0.0f;
    }

    int s = v;
    #pragma unroll
    for (int o = 1; o < 32; o <<= 1) {
        int u = __shfl_up_sync(0xffffffffu, s, o);
        if (lane >= o) s += u;
    }
    if (lane == 31) wsum[wid] = s;
    __syncthreads();
    if (wid == 0) {
        int ws = wsum[lane];
        int p = ws;
        #pragma unroll
        for (int o = 1; o < 32; o <<= 1) {
            int u = __shfl_up_sync(0xffffffffu, p, o);
            if (lane >= o) p += u;
        }
        wsum[lane] = p - ws;
    }
    __syncthreads();
    int excl = s - v + wsum[wid];
    if (t == SCAN_B - 1) sh_agg = excl + v;
    __syncthreads();

    if (t == 0) {
        unsigned int A = (unsigned int)sh_agg;
        if (b == 0) {
            atomicExch(&g_state[0], (2u << 30) | A);
            sh_prefix = 0;
        } else {
            atomicExch(&g_state[b], (1u << 30) | A);
            unsigned int prefix = 0;
            int j = b - 1;
            while (true) {
                unsigned int st = atomicAdd(&g_state[j], 0u);
                unsigned int f = st >> 30;
                if (f == 2u) { prefix += st & 0x3FFFFFFFu; break; }
                if (f == 1u) { prefix += st & 0x3FFFFFFFu; j--; }
            }
            atomicExch(&g_state[b], (2u << 30) | (prefix + A));
            sh_prefix = (int)prefix;
        }
    }
    __syncthreads();
    if (i < N) g_offcnt[i] = make_int2(excl + sh_prefix, v);
}

// ---------------- fill CSR edge records (no atomics; norm pre-packed as half2) ----------------
__global__ void fill_kernel(const int* __restrict__ ei, const float* __restrict__ ew, int E) {
    int e = blockIdx.x * blockDim.x + threadIdx.x;
    if (e >= E) return;
    int r = ei[e];
    int c = ei[E + e];
    float nrm = g_dinv[r] * ew[e] * g_dinv[c];
    __half2 nh = __float2half2_rn(nrm);
    int p = g_offcnt[c].x + g_slot[e];
    g_edges[p] = make_int2(r, (int)*(uint32_t*)&nh);
}

// ================= GEMM: h = fp16(x) @ fp16(W), mma.sync + ldmatrix =================
#define ROWB 272                    // 136 halfs per padded row (272 bytes)
#define GS_A  0                     // 64 rows  * 272B = 17408
#define GS_WH 17408                 // 128 rows * 272B = 34816
#define GS_TOTAL 52224

__device__ __forceinline__ void mma16816f16(float* c, const uint32_t* a, uint32_t b0, uint32_t b1) {
    asm volatile(
        "mma.sync.aligned.m16n8k16.row.col.f32.f16.f16.f32 "
        "{%0,%1,%2,%3}, {%4,%5,%6,%7}, {%8,%9}, {%0,%1,%2,%3};"
        : "+f"(c[0]), "+f"(c[1]), "+f"(c[2]), "+f"(c[3])
        : "r"(a[0]), "r"(a[1]), "r"(a[2]), "r"(a[3]), "r"(b0), "r"(b1));
}

__device__ __forceinline__ void ldsm_x4(uint32_t& r0, uint32_t& r1, uint32_t& r2, uint32_t& r3,
                                        uint32_t addr) {
    asm volatile("ldmatrix.sync.aligned.m8n8.x4.shared.b16 {%0,%1,%2,%3}, [%4];"
                 : "=r"(r0), "=r"(r1), "=r"(r2), "=r"(r3) : "r"(addr));
}

__global__ __launch_bounds__(256) void gemm_kernel(const float* __restrict__ x, int N) {
    extern __shared__ char smem[];
    uint32_t sb = (uint32_t)__cvta_generic_to_shared(smem);
    const int tid = threadIdx.x;
    const int row0 = blockIdx.x * 64;

    const float4* xv = (const float4*)x;
    #pragma unroll
    for (int u = tid; u < 1024; u += 256) {
        int r = u >> 4, q = u & 15;
        float4 a = make_float4(0.f, 0.f, 0.f, 0.f);
        float4 b = make_float4(0.f, 0.f, 0.f, 0.f);
        if (row0 + r < N) {
            a = __ldcs(&xv[(size_t)(row0 + r) * 32 + q * 2]);
            b = __ldcs(&xv[(size_t)(row0 + r) * 32 + q * 2 + 1]);
        }
        uint4 val; __half2 h;
        h = __floats2half2_rn(a.x, a.y); val.x = *(uint32_t*)&h;
        h = __floats2half2_rn(a.z, a.w); val.y = *(uint32_t*)&h;
        h = __floats2half2_rn(b.x, b.y); val.z = *(uint32_t*)&h;
        h = __floats2half2_rn(b.z, b.w); val.w = *(uint32_t*)&h;
        *(uint4*)(smem + GS_A + r * ROWB + q * 16) = val;
    }
    const uint4* wh = (const uint4*)g_Wt;
    #pragma unroll
    for (int u = tid; u < 2048; u += 256) {
        int n = u >> 4, q = u & 15;
        *(uint4*)(smem + GS_WH + n * ROWB + q * 16) = wh[u];
    }
    __syncthreads();

    const int warp = tid >> 5, lane = tid & 31;
    const int wm = warp >> 2, wn = warp & 3;

    uint32_t aAddr[2];
    #pragma unroll
    for (int i = 0; i < 2; i++) {
        int r = wm * 32 + i * 16 + (lane & 15);
        aAddr[i] = sb + GS_A + r * ROWB + ((lane >> 4) * 8) * 2;
    }
    uint32_t bRow = (uint32_t)(wn * 32 + ((lane >> 4) << 3) + (lane & 7));
    uint32_t bCol = (uint32_t)(((lane >> 3) & 1) * 8) * 2;
    uint32_t bAddr[2];
    #pragma unroll
    for (int jp = 0; jp < 2; jp++)
        bAddr[jp] = sb + GS_WH + (bRow + jp * 16) * ROWB + bCol;

    float acc[2][4][4];
    #pragma unroll
    for (int i = 0; i < 2; i++)
        #pragma unroll
        for (int j = 0; j < 4; j++)
            #pragma unroll
            for (int q = 0; q < 4; q++) acc[i][j][q] = 0.0f;

    #pragma unroll
    for (int ks = 0; ks < 8; ks++) {
        const uint32_t koff = ks * 32;
        uint32_t ah[2][4];
        ldsm_x4(ah[0][0], ah[0][1], ah[0][2], ah[0][3], aAddr[0] + koff);
        ldsm_x4(ah[1][0], ah[1][1], ah[1][2], ah[1][3], aAddr[1] + koff);

        uint32_t bh[8];
        ldsm_x4(bh[0], bh[1], bh[2], bh[3], bAddr[0] + koff);
        ldsm_x4(bh[4], bh[5], bh[6], bh[7], bAddr[1] + koff);

        #pragma unroll
        for (int j = 0; j < 4; j++) {
            #pragma unroll
            for (int i = 0; i < 2; i++)
                mma16816f16(acc[i][j], ah[i], bh[j * 2], bh[j * 2 + 1]);
        }
    }

    const int g = lane >> 2, c = lane & 3;
    #pragma unroll
    for (int i = 0; i < 2; i++) {
        int r = row0 + wm * 32 + i * 16 + g;
        #pragma unroll
        for (int j = 0; j < 4; j++) {
            int ncol = wn * 32 + j * 8 + 2 * c;
            if (r < N)
                *(__half2*)&g_h[(size_t)r * DIM + ncol] = __floats2half2_rn(acc[i][j][0], acc[i][j][1]);
            if (r + 8 < N)
                *(__half2*)&g_h[(size_t)(r + 8) * DIM + ncol] = __floats2half2_rn(acc[i][j][2], acc[i][j][3]);
        }
    }
}

// ---------------- gather + bias + LayerNorm + GELU + residual (one warp per node) ----------------
__device__ __forceinline__ void hfma_row(__half2& a01, __half2& a23, uint2 u, uint32_t nbits) {
    __half2 n = *(__half2*)&nbits;
    a01 = __hfma2(*(__half2*)&u.x, n, a01);
    a23 = __hfma2(*(__half2*)&u.y, n, a23);
}

__device__ __forceinline__ void fold(float4& acc, __half2 a01, __half2 a23) {
    float2 f01 = __half22float2(a01);
    float2 f23 = __half22float2(a23);
    acc.x += f01.x; acc.y += f01.y; acc.z += f23.x; acc.w += f23.y;
}

__global__ __launch_bounds__(256) void gather_ln_kernel(
    const float4* __restrict__ x, float4* __restrict__ out,
    const float4* __restrict__ b, const float4* __restrict__ gamma,
    const float4* __restrict__ beta, int N)
{
    int w = (blockIdx.x * blockDim.x + threadIdx.x) >> 5;
    int lane = threadIdx.x & 31;
    if (w >= N) return;

    int2 oc = g_offcnt[w];
    int s0 = oc.x, cnt = oc.y;
    int end = s0 + cnt;

    float4 acc = b[lane];
    const uint2* hv = (const uint2*)g_h;
    const __half2 hz = __floats2half2_rn(0.f, 0.f);

    // clean 4-batches: half2 accumulate, fold to fp32 per batch
    int e = s0;
    int nfull = cnt & ~3;
    for (int stop = s0 + nfull; e < stop; e += 4) {
        int2 d0 = g_edges[e];
        int2 d1 = g_edges[e + 1];
        int2 d2 = g_edges[e + 2];
        int2 d3 = g_edges[e + 3];
        uint2 v0 = hv[(size_t)d0.x * 32 + lane];
        uint2 v1 = hv[(size_t)d1.x * 32 + lane];
        uint2 v2 = hv[(size_t)d2.x * 32 + lane];
        uint2 v3 = hv[(size_t)d3.x * 32 + lane];
        __half2 a01 = hz, a23 = hz;
        hfma_row(a01, a23, v0, (uint32_t)d0.y);
        hfma_row(a01, a23, v1, (uint32_t)d1.y);
        hfma_row(a01, a23, v2, (uint32_t)d2.y);
        hfma_row(a01, a23, v3, (uint32_t)d3.y);
        fold(acc, a01, a23);
    }
    // one clamped batch for the 1-3 edge tail (zeroed norms)
    if (e < end) {
        int e1 = e + 1 < end ? e + 1 : end - 1;
        int e2 = e + 2 < end ? e + 2 : end - 1;
        int2 d0 = g_edges[e];
        int2 d1 = g_edges[e1];
        int2 d2 = g_edges[e2];
        uint32_t n0 = (uint32_t)d0.y;
        uint32_t n1 = (e + 1 < end) ? (uint32_t)d1.y : 0u;
        uint32_t n2 = (e + 2 < end) ? (uint32_t)d2.y : 0u;
        uint2 v0 = hv[(size_t)d0.x * 32 + lane];
        uint2 v1 = hv[(size_t)d1.x * 32 + lane];
        uint2 v2 = hv[(size_t)d2.x * 32 + lane];
        __half2 a01 = hz, a23 = hz;
        hfma_row(a01, a23, v0, n0);
        hfma_row(a01, a23, v1, n1);
        hfma_row(a01, a23, v2, n2);
        fold(acc, a01, a23);
    }

    float s = acc.x + acc.y + acc.z + acc.w;
    #pragma unroll
    for (int off = 16; off > 0; off >>= 1) s += __shfl_xor_sync(0xffffffffu, s, off);
    float mu = s * (1.0f / 128.0f);

    float dx = acc.x - mu, dy = acc.y - mu, dz = acc.z - mu, dw = acc.w - mu;
    float sq = dx * dx + dy * dy + dz * dz + dw * dw;
    #pragma unroll
    for (int off = 16; off > 0; off >>= 1) sq += __shfl_xor_sync(0xffffffffu, sq, off);
    float rinv = rsqrtf(sq * (1.0f / 128.0f) + 1e-5f);

    float4 gm = gamma[lane];
    float4 bt = beta[lane];
    float4 xv = __ldcs(&x[(size_t)w * 32 + lane]);

    float4 o;
    {
        float t = dx * rinv * gm.x + bt.x;
        o.x = xv.x + 0.5f * t * (1.0f + erff(t * 0.70710678118654752f));
        t = dy * rinv * gm.y + bt.y;
        o.y = xv.y + 0.5f * t * (1.0f + erff(t * 0.70710678118654752f));
        t = dz * rinv * gm.z + bt.z;
        o.z = xv.z + 0.5f * t * (1.0f + erff(t * 0.70710678118654752f));
        t = dw * rinv * gm.w + bt.w;
        o.w = xv.w + 0.5f * t * (1.0f + erff(t * 0.70710678118654752f));
    }
    __stcs(&out[(size_t)w * 32 + lane], o);
}

// ---------------- launch ----------------
extern "C" void kernel_launch(void* const* d_in, const int* in_sizes, int n_in,
                              void* d_out, int out_size) {
    const float* x = (const float*)d_in[0];
    const int* ei = (const int*)d_in[1];
    const float* ew = (const float*)d_in[2];
    const float* W = (const float*)d_in[3];
    const float* b = (const float*)d_in[4];
    const float* gamma = (const float*)d_in[5];
    const float* beta = (const float*)d_in[6];
    float* out = (float*)d_out;

    int N = in_sizes[0] / DIM;
    int E = in_sizes[1] / 2;   // edge_index delivered as int32 [2, E]
    int nb = (N + SCAN_B - 1) / SCAN_B;

    static cudaStream_t s_side = nullptr;
    static cudaEvent_t ev_init = nullptr, ev_gemm = nullptr;
    if (!s_side) {
        cudaStreamCreateWithFlags(&s_side, cudaStreamNonBlocking);
        cudaEventCreateWithFlags(&ev_init, cudaEventDisableTiming);
        cudaEventCreateWithFlags(&ev_gemm, cudaEventDisableTiming);
        cudaFuncSetAttribute(gemm_kernel, cudaFuncAttributeMaxDynamicSharedMemorySize, GS_TOTAL);
    }

    // launch 1 (main): fused init + W convert
    initwsplit_kernel<<<(N + 255) / 256, 256>>>(W, N);
    cudaEventRecord(ev_init, 0);

    // launches 2,3 (main): deg(+slot, packed) -> single-pass scan(+dinv)
    deg_kernel<<<(E + 255) / 256, 256>>>(ei + E, ew, E);
    scanlb_kernel<<<nb, SCAN_B>>>(N);

    // launch 4 (side): ldmatrix GEMM, overlapped with CSR chain
    cudaStreamWaitEvent(s_side, ev_init, 0);
    gemm_kernel<<<(N + 63) / 64, 256, GS_TOTAL, s_side>>>(x, N);
    cudaEventRecord(ev_gemm, s_side);

    // launch 5 (main): fill
    fill_kernel<<<(E + 255) / 256, 256>>>(ei, ew, E);

    // launch 6 (main): join, fused gather + LN + GELU + residual
    cudaStreamWaitEvent(0, ev_gemm, 0);
    gather_ln_kernel<<<(N + 7) / 8, 256>>>((const float4*)x, (float4*)out,
                                           (const float4*)b, (const float4*)gamma,
                                           (const float4*)beta, N);
}